// round 2
// baseline (speedup 1.0000x reference)
#include <cuda_runtime.h>
#include <math.h>

#define SEQ_    2048
#define DIN_    2048
#define NH_     32
#define NKV_    8
#define HD_     64
#define DKV_    (NKV_*HD_)   // 512
#define DOUT_   (NH_*HD_)    // 2048

// Scratch (allocation-free rule: __device__ globals)
__device__ float g_Q[SEQ_*DOUT_];   // [S, H*D] post-proj, then normed+roped in place
__device__ float g_K[SEQ_*DKV_];
__device__ float g_V[SEQ_*DKV_];
__device__ float g_A[SEQ_*DOUT_];   // attention output [S, H*D]

// ---------------------------------------------------------------------------
// Tiled fp32 SGEMM: C[M,N] = A[M,K] @ B[K,N], all row-major.
// BM=BN=128, BK=16, 256 threads, 8x8 per thread. Requires M%128==0, N%128==0,
// K%16==0 (all satisfied here: K=2048, N in {512,2048,3072-split}).
// ---------------------------------------------------------------------------
__global__ __launch_bounds__(256) void sgemm128(const float* __restrict__ A,
                                                const float* __restrict__ B,
                                                float* __restrict__ C,
                                                int M, int N, int K) {
    __shared__ float As[16][128];   // transposed: As[k][m]
    __shared__ float Bs[16][128];

    const int tid = threadIdx.x;
    const int bm = blockIdx.y * 128;
    const int bn = blockIdx.x * 128;

    const int tr = (tid / 16) * 8;   // row of 8x8 tile
    const int tc = (tid % 16) * 8;   // col of 8x8 tile

    float acc[8][8];
#pragma unroll
    for (int i = 0; i < 8; i++)
#pragma unroll
        for (int j = 0; j < 8; j++) acc[i][j] = 0.f;

    for (int kt = 0; kt < K; kt += 16) {
        // Load A tile (128x16) transposed into As
#pragma unroll
        for (int l = 0; l < 2; l++) {
            int idx = tid * 4 + l * 1024;
            int r = idx >> 4, c = idx & 15;
            float4 v = *(const float4*)(A + (size_t)(bm + r) * K + kt + c);
            As[c + 0][r] = v.x;
            As[c + 1][r] = v.y;
            As[c + 2][r] = v.z;
            As[c + 3][r] = v.w;
        }
        // Load B tile (16x128)
#pragma unroll
        for (int l = 0; l < 2; l++) {
            int idx = tid * 4 + l * 1024;
            int r = idx >> 7, c = idx & 127;
            *(float4*)&Bs[r][c] = *(const float4*)(B + (size_t)(kt + r) * N + bn + c);
        }
        __syncthreads();

#pragma unroll
        for (int k = 0; k < 16; k++) {
            float ar[8], br[8];
#pragma unroll
            for (int i = 0; i < 8; i++) ar[i] = As[k][tr + i];
#pragma unroll
            for (int j = 0; j < 8; j++) br[j] = Bs[k][tc + j];
#pragma unroll
            for (int i = 0; i < 8; i++)
#pragma unroll
                for (int j = 0; j < 8; j++)
                    acc[i][j] = fmaf(ar[i], br[j], acc[i][j]);
        }
        __syncthreads();
    }

#pragma unroll
    for (int i = 0; i < 8; i++)
#pragma unroll
        for (int j = 0; j < 8; j += 4) {
            float4 v = make_float4(acc[i][j], acc[i][j + 1], acc[i][j + 2], acc[i][j + 3]);
            *(float4*)(C + (size_t)(bm + tr + i) * N + bn + tc + j) = v;
        }
}

// ---------------------------------------------------------------------------
// Fused RMSNorm (per head, eps=1e-6) + RoPE (rotate_half), in place.
// One warp per (token, head). Lane handles dims d and d+32.
// ---------------------------------------------------------------------------
__global__ void norm_rope(float* __restrict__ X, const float* __restrict__ w,
                          const float* __restrict__ cosp, const float* __restrict__ sinp,
                          int nheads, int rowdim) {
    int gwarp = (blockIdx.x * blockDim.x + threadIdx.x) >> 5;
    int lane = threadIdx.x & 31;
    int s = gwarp / nheads;
    int h = gwarp % nheads;
    if (s >= SEQ_) return;

    float* p = X + (size_t)s * rowdim + h * HD_;
    float x0 = p[lane];
    float x1 = p[lane + 32];

    float ss = x0 * x0 + x1 * x1;
#pragma unroll
    for (int off = 16; off; off >>= 1) ss += __shfl_xor_sync(0xFFFFFFFFu, ss, off);
    float r = rsqrtf(ss * (1.f / 64.f) + 1e-6f);

    x0 = x0 * r * w[lane];
    x1 = x1 * r * w[lane + 32];

    float c0 = cosp[s * HD_ + lane],      s0 = sinp[s * HD_ + lane];
    float c1 = cosp[s * HD_ + lane + 32], s1 = sinp[s * HD_ + lane + 32];

    p[lane]      = x0 * c0 - x1 * s0;   // lower half: x*cos - x_hi*sin
    p[lane + 32] = x1 * c1 + x0 * s1;   // upper half: x*cos + x_lo*sin
}

// ---------------------------------------------------------------------------
// Causal GQA flash attention. 128 queries per block, one query per thread.
// K/V tiles of 32 keys staged in smem (broadcast reads), q/o/s in registers.
// ---------------------------------------------------------------------------
#define FA_BQ 128
#define FA_BK 32

__global__ __launch_bounds__(FA_BQ) void flash_attn() {
    const int h = blockIdx.y;
    const int q0 = blockIdx.x * FA_BQ;
    const int kvh = h >> 2;           // GQA group of 4
    const int tid = threadIdx.x;
    const int qi = q0 + tid;

    __shared__ float Ks[FA_BK][HD_];
    __shared__ float Vs[FA_BK][HD_];

    float q[HD_], o[HD_];
    const float scale = 0.125f;       // 1/sqrt(64)
#pragma unroll
    for (int d = 0; d < HD_; d++) {
        q[d] = g_Q[(size_t)qi * DOUT_ + h * HD_ + d] * scale;
        o[d] = 0.f;
    }
    float m = -1e30f, l = 0.f;

    const int kend = q0 + FA_BQ;      // keys needed: <= q0+127
    for (int k0 = 0; k0 < kend; k0 += FA_BK) {
        __syncthreads();
#pragma unroll
        for (int t = 0; t < 4; t++) { // 32*64 floats = 512 float4, 4 per thread
            int idx = (tid + t * 128) * 4;
            int r = idx >> 6, c = idx & 63;
            *(float4*)&Ks[r][c] = *(const float4*)&g_K[(size_t)(k0 + r) * DKV_ + kvh * HD_ + c];
            *(float4*)&Vs[r][c] = *(const float4*)&g_V[(size_t)(k0 + r) * DKV_ + kvh * HD_ + c];
        }
        __syncthreads();

        float s[FA_BK];
        float mt = m;
#pragma unroll 4
        for (int j = 0; j < FA_BK; j++) {
            float acc = 0.f;
#pragma unroll
            for (int d = 0; d < HD_; d++) acc = fmaf(q[d], Ks[j][d], acc);
            s[j] = (k0 + j <= qi) ? acc : -1e30f;
            mt = fmaxf(mt, s[j]);
        }

        float corr = __expf(m - mt);
        m = mt;
        l *= corr;
#pragma unroll
        for (int d = 0; d < HD_; d++) o[d] *= corr;

#pragma unroll 4
        for (int j = 0; j < FA_BK; j++) {
            float p = __expf(s[j] - m);
            l += p;
#pragma unroll
            for (int d = 0; d < HD_; d++) o[d] = fmaf(p, Vs[j][d], o[d]);
        }
    }

    float inv = 1.f / l;
#pragma unroll
    for (int d = 0; d < HD_; d++)
        g_A[(size_t)qi * DOUT_ + h * HD_ + d] = o[d] * inv;
}

// ---------------------------------------------------------------------------
extern "C" void kernel_launch(void* const* d_in, const int* in_sizes, int n_in,
                              void* d_out, int out_size) {
    const float* x    = (const float*)d_in[0];
    const float* cosp = (const float*)d_in[1];
    const float* sinp = (const float*)d_in[2];
    const float* wq   = (const float*)d_in[3];
    const float* wk   = (const float*)d_in[4];
    const float* wv   = (const float*)d_in[5];
    const float* wo   = (const float*)d_in[6];
    const float* qw   = (const float*)d_in[7];
    const float* kw   = (const float*)d_in[8];
    float* out = (float*)d_out;

    float *Q, *K, *V, *A;
    cudaGetSymbolAddress((void**)&Q, g_Q);
    cudaGetSymbolAddress((void**)&K, g_K);
    cudaGetSymbolAddress((void**)&V, g_V);
    cudaGetSymbolAddress((void**)&A, g_A);

    // QKV projections
    sgemm128<<<dim3(DOUT_ / 128, SEQ_ / 128), 256>>>(x, wq, Q, SEQ_, DOUT_, DIN_);
    sgemm128<<<dim3(DKV_ / 128, SEQ_ / 128), 256>>>(x, wk, K, SEQ_, DKV_, DIN_);
    sgemm128<<<dim3(DKV_ / 128, SEQ_ / 128), 256>>>(x, wv, V, SEQ_, DKV_, DIN_);

    // RMSNorm + RoPE (in place on Q, K)
    norm_rope<<<(SEQ_ * NH_ * 32) / 256, 256>>>(Q, qw, cosp, sinp, NH_, DOUT_);
    norm_rope<<<(SEQ_ * NKV_ * 32) / 256, 256>>>(K, kw, cosp, sinp, NKV_, DKV_);

    // Causal GQA attention
    flash_attn<<<dim3(SEQ_ / FA_BQ, NH_), FA_BQ>>>();

    // Output projection
    sgemm128<<<dim3(DIN_ / 128, SEQ_ / 128), 256>>>(A, wo, out, SEQ_, DIN_, DOUT_);
}

// round 6
// speedup vs baseline: 1.8953x; 1.8953x over previous
#include <cuda_runtime.h>
#include <cstdint>
#include <math.h>

#define SEQ_    2048
#define DIN_    2048
#define NH_     32
#define NKV_    8
#define HD_     64
#define DQKV_   3072            // Q(2048) | K(512) | V(512) fused columns
#define DOUT_   2048
#define GK_     2048            // GEMM K (both GEMMs have K=2048)

// ---------------------------------------------------------------------------
// Scratch (__device__ globals; allocation-free rule)
// ---------------------------------------------------------------------------
__device__ float g_xr[SEQ_ * DIN_];        // x rounded to tf32 grid
__device__ float g_wt[DQKV_ * DIN_];       // W_qkv^T [3072][2048], tf32-rounded
__device__ float g_wot[DIN_ * DOUT_];      // Wo^T    [2048][2048], tf32-rounded
__device__ float g_QKV[SEQ_ * DQKV_];      // [S, 3072]: Q | K | V
__device__ float g_A[SEQ_ * DOUT_];        // attention out, tf32-rounded

// ---------------------------------------------------------------------------
// Helpers (baseline PTX only — compute_103 has no 'a' features)
// ---------------------------------------------------------------------------
__device__ __forceinline__ uint32_t smem_u32(const void* p) {
    uint32_t a;
    asm("{ .reg .u64 t; cvta.to.shared.u64 t, %1; cvt.u32.u64 %0, t; }" : "=r"(a) : "l"(p));
    return a;
}
__device__ __forceinline__ float rnd_tf32(float f) {
    uint32_t u;
    asm("cvt.rna.tf32.f32 %0, %1;" : "=r"(u) : "f"(f));
    return __uint_as_float(u);
}
__device__ __forceinline__ void cpasync16(uint32_t dst, const void* src) {
    asm volatile("cp.async.cg.shared.global [%0], [%1], 16;" :: "r"(dst), "l"(src));
}
#define CP_COMMIT()  asm volatile("cp.async.commit_group;" ::: "memory")
#define CP_WAIT(n)   asm volatile("cp.async.wait_group %0;" :: "n"(n) : "memory")

__device__ __forceinline__ void mma_tf32(float* d, const float* a, const float* b) {
    asm volatile(
        "mma.sync.aligned.m16n8k8.row.col.f32.tf32.tf32.f32 "
        "{%0,%1,%2,%3}, {%4,%5,%6,%7}, {%8,%9}, {%0,%1,%2,%3};"
        : "+f"(d[0]), "+f"(d[1]), "+f"(d[2]), "+f"(d[3])
        : "r"(__float_as_uint(a[0])), "r"(__float_as_uint(a[1])),
          "r"(__float_as_uint(a[2])), "r"(__float_as_uint(a[3])),
          "r"(__float_as_uint(b[0])), "r"(__float_as_uint(b[1])));
}

// ---------------------------------------------------------------------------
// Prep kernels: tf32-round copy, and transpose+round for weights
// ---------------------------------------------------------------------------
__global__ void cvt_round4(const float* __restrict__ src, float* __restrict__ dst, int n4) {
    int i = blockIdx.x * blockDim.x + threadIdx.x;
    if (i >= n4) return;
    float4 v = ((const float4*)src)[i];
    v.x = rnd_tf32(v.x); v.y = rnd_tf32(v.y);
    v.z = rnd_tf32(v.z); v.w = rnd_tf32(v.w);
    ((float4*)dst)[i] = v;
}

// W[K=2048, ncols] -> out[(row_off+n)*2048 + k], tf32-rounded
__global__ void tposer(const float* __restrict__ W, int ncols,
                       float* __restrict__ out, int row_off) {
    __shared__ float t[32][33];
    int tx = threadIdx.x, ty = threadIdx.y;
    int x = blockIdx.x * 32 + tx;         // col (n)
    int y = blockIdx.y * 32 + ty;         // row (k)
#pragma unroll
    for (int i = 0; i < 32; i += 8)
        t[ty + i][tx] = W[(size_t)(y + i) * ncols + x];
    __syncthreads();
    int n = blockIdx.x * 32 + ty;
    int k = blockIdx.y * 32 + tx;
#pragma unroll
    for (int i = 0; i < 32; i += 8)
        out[(size_t)(row_off + n + i) * GK_ + k] = rnd_tf32(t[tx][ty + i]);
}

// ---------------------------------------------------------------------------
// tf32 mma.sync GEMM: C[M,N] = A[M,2048] @ Bt[N,2048]^T  (A,Bt row-major,
// K-contiguous, pre-rounded to tf32). CTA tile 128x128, BK=32, 8 warps
// (2x4, warp tile 64x32), cp.async double buffer.
// ---------------------------------------------------------------------------
#define NCH32_  (GK_ / 32)     // 64
#define KPAD_   36             // padded k-stride (floats)
#define STG_F_  (2 * 128 * KPAD_)   // floats per stage (As + Bs) = 9216

__global__ __launch_bounds__(256) void gemm_tf32(
    const float* __restrict__ A, const float* __restrict__ Bt,
    float* __restrict__ C, int ldc)
{
    extern __shared__ float sm[];
    const int tid = threadIdx.x;
    const int wid = tid >> 5, lane = tid & 31;
    const int bm = blockIdx.y * 128, bn = blockIdx.x * 128;
    const int warp_m = (wid & 1) * 64, warp_n = (wid >> 1) * 32;
    const int tr = lane >> 2, tc = lane & 3;

    float acc[4][4][4];
#pragma unroll
    for (int i = 0; i < 4; i++)
#pragma unroll
        for (int j = 0; j < 4; j++)
#pragma unroll
            for (int r = 0; r < 4; r++) acc[i][j][r] = 0.f;

    const float* Ag = A + (size_t)bm * GK_;
    const float* Bg = Bt + (size_t)bn * GK_;

    // per-thread load slots: idx in [0,1024), row = idx>>3, q = idx&7
    const int lrow = tid >> 3;              // base rows (4 apart via +=32)
    const int lq = tid & 7;

    uint32_t sbase = smem_u32(sm);

    // ---- prefetch stage 0 ----
    {
        uint32_t sA = sbase;
        uint32_t sB = sbase + 128 * KPAD_ * 4;
#pragma unroll
        for (int i = 0; i < 4; i++) {
            int row = lrow + i * 32;
            uint32_t off = (uint32_t)(row * KPAD_ + lq * 4) * 4;
            cpasync16(sA + off, Ag + (size_t)row * GK_ + lq * 4);
            cpasync16(sB + off, Bg + (size_t)row * GK_ + lq * 4);
        }
        CP_COMMIT();
    }

    for (int c = 0; c < NCH32_; c++) {
        if (c + 1 < NCH32_) {
            const int k0 = (c + 1) * 32;
            uint32_t sA = sbase + (uint32_t)((c + 1) & 1) * STG_F_ * 4;
            uint32_t sB = sA + 128 * KPAD_ * 4;
#pragma unroll
            for (int i = 0; i < 4; i++) {
                int row = lrow + i * 32;
                uint32_t off = (uint32_t)(row * KPAD_ + lq * 4) * 4;
                cpasync16(sA + off, Ag + (size_t)row * GK_ + k0 + lq * 4);
                cpasync16(sB + off, Bg + (size_t)row * GK_ + k0 + lq * 4);
            }
            CP_COMMIT();
            CP_WAIT(1);
        } else {
            CP_WAIT(0);
        }
        __syncthreads();

        const float* As = sm + (c & 1) * STG_F_;
        const float* Bs = As + 128 * KPAD_;

#pragma unroll
        for (int kk = 0; kk < 4; kk++) {
            const int kb = kk * 8;
            float a[4][4], b[4][2];
#pragma unroll
            for (int mt = 0; mt < 4; mt++) {
                const float* ap = As + (warp_m + mt * 16 + tr) * KPAD_ + kb + tc;
                a[mt][0] = ap[0];
                a[mt][1] = ap[8 * KPAD_];
                a[mt][2] = ap[4];
                a[mt][3] = ap[8 * KPAD_ + 4];
            }
#pragma unroll
            for (int nt = 0; nt < 4; nt++) {
                const float* bp = Bs + (warp_n + nt * 8 + tr) * KPAD_ + kb + tc;
                b[nt][0] = bp[0];
                b[nt][1] = bp[4];
            }
#pragma unroll
            for (int mt = 0; mt < 4; mt++)
#pragma unroll
                for (int nt = 0; nt < 4; nt++)
                    mma_tf32(acc[mt][nt], a[mt], b[nt]);
        }
        __syncthreads();
    }

    // ---- epilogue ----
#pragma unroll
    for (int mt = 0; mt < 4; mt++)
#pragma unroll
        for (int nt = 0; nt < 4; nt++) {
            int row = bm + warp_m + mt * 16 + tr;
            int col = bn + warp_n + nt * 8 + 2 * tc;
            *(float2*)(C + (size_t)row * ldc + col) =
                make_float2(acc[mt][nt][0], acc[mt][nt][1]);
            *(float2*)(C + (size_t)(row + 8) * ldc + col) =
                make_float2(acc[mt][nt][2], acc[mt][nt][3]);
        }
}

// ---------------------------------------------------------------------------
// Fused RMSNorm + RoPE, in place on a column slice of g_QKV.
// ---------------------------------------------------------------------------
__global__ void norm_rope(float* __restrict__ X, const float* __restrict__ w,
                          const float* __restrict__ cosp, const float* __restrict__ sinp,
                          int nheads, int rowdim) {
    int gwarp = (blockIdx.x * blockDim.x + threadIdx.x) >> 5;
    int lane = threadIdx.x & 31;
    int s = gwarp / nheads;
    int h = gwarp % nheads;
    if (s >= SEQ_) return;

    float* p = X + (size_t)s * rowdim + h * HD_;
    float x0 = p[lane];
    float x1 = p[lane + 32];

    float ss = x0 * x0 + x1 * x1;
#pragma unroll
    for (int off = 16; off; off >>= 1) ss += __shfl_xor_sync(0xFFFFFFFFu, ss, off);
    float r = rsqrtf(ss * (1.f / 64.f) + 1e-6f);

    x0 = x0 * r * w[lane];
    x1 = x1 * r * w[lane + 32];

    float c0 = cosp[s * HD_ + lane],      s0 = sinp[s * HD_ + lane];
    float c1 = cosp[s * HD_ + lane + 32], s1 = sinp[s * HD_ + lane + 32];

    p[lane]      = x0 * c0 - x1 * s0;
    p[lane + 32] = x1 * c1 + x0 * s1;
}

// ---------------------------------------------------------------------------
// Causal GQA flash attention (fp32 SIMT). Reads g_QKV (stride 3072).
// Output rounded to tf32 grid (feeds tf32 GEMM).
// ---------------------------------------------------------------------------
#define FA_BQ 128
#define FA_BK 32

__global__ __launch_bounds__(FA_BQ) void flash_attn() {
    const int h = blockIdx.y;
    const int q0 = blockIdx.x * FA_BQ;
    const int kvh = h >> 2;
    const int tid = threadIdx.x;
    const int qi = q0 + tid;

    __shared__ float Ks[FA_BK][HD_];
    __shared__ float Vs[FA_BK][HD_];

    float q[HD_], o[HD_];
    const float scale = 0.125f;
#pragma unroll
    for (int d = 0; d < HD_; d++) {
        q[d] = g_QKV[(size_t)qi * DQKV_ + h * HD_ + d] * scale;
        o[d] = 0.f;
    }
    float m = -1e30f, l = 0.f;

    const int kend = q0 + FA_BQ;
    for (int k0 = 0; k0 < kend; k0 += FA_BK) {
        __syncthreads();
#pragma unroll
        for (int t = 0; t < 4; t++) {
            int idx = (tid + t * 128) * 4;
            int r = idx >> 6, c = idx & 63;
            *(float4*)&Ks[r][c] =
                *(const float4*)&g_QKV[(size_t)(k0 + r) * DQKV_ + 2048 + kvh * HD_ + c];
            *(float4*)&Vs[r][c] =
                *(const float4*)&g_QKV[(size_t)(k0 + r) * DQKV_ + 2560 + kvh * HD_ + c];
        }
        __syncthreads();

        float s[FA_BK];
        float mt = m;
#pragma unroll 4
        for (int j = 0; j < FA_BK; j++) {
            float acc = 0.f;
#pragma unroll
            for (int d = 0; d < HD_; d++) acc = fmaf(q[d], Ks[j][d], acc);
            s[j] = (k0 + j <= qi) ? acc : -1e30f;
            mt = fmaxf(mt, s[j]);
        }

        float corr = __expf(m - mt);
        m = mt;
        l *= corr;
#pragma unroll
        for (int d = 0; d < HD_; d++) o[d] *= corr;

#pragma unroll 4
        for (int j = 0; j < FA_BK; j++) {
            float p = __expf(s[j] - m);
            l += p;
#pragma unroll
            for (int d = 0; d < HD_; d++) o[d] = fmaf(p, Vs[j][d], o[d]);
        }
    }

    float inv = 1.f / l;
#pragma unroll
    for (int d = 0; d < HD_; d++)
        g_A[(size_t)qi * DOUT_ + h * HD_ + d] = rnd_tf32(o[d] * inv);
}

// ---------------------------------------------------------------------------
extern "C" void kernel_launch(void* const* d_in, const int* in_sizes, int n_in,
                              void* d_out, int out_size) {
    const float* x    = (const float*)d_in[0];
    const float* cosp = (const float*)d_in[1];
    const float* sinp = (const float*)d_in[2];
    const float* wq   = (const float*)d_in[3];
    const float* wk   = (const float*)d_in[4];
    const float* wv   = (const float*)d_in[5];
    const float* wo   = (const float*)d_in[6];
    const float* qw   = (const float*)d_in[7];
    const float* kw   = (const float*)d_in[8];
    float* out = (float*)d_out;

    float *xr, *wt, *wot, *QKV, *A;
    cudaGetSymbolAddress((void**)&xr,  g_xr);
    cudaGetSymbolAddress((void**)&wt,  g_wt);
    cudaGetSymbolAddress((void**)&wot, g_wot);
    cudaGetSymbolAddress((void**)&QKV, g_QKV);
    cudaGetSymbolAddress((void**)&A,   g_A);

    const int smem_sz = 2 * STG_F_ * 4;   // 73728 B
    cudaFuncSetAttribute(gemm_tf32, cudaFuncAttributeMaxDynamicSharedMemorySize, smem_sz);

    // Prep: round x; transpose+round weights
    cvt_round4<<<(SEQ_ * DIN_ / 4 + 255) / 256, 256>>>(x, xr, SEQ_ * DIN_ / 4);
    tposer<<<dim3(2048 / 32, DIN_ / 32),  dim3(32, 8)>>>(wq, 2048, wt, 0);
    tposer<<<dim3(512 / 32,  DIN_ / 32),  dim3(32, 8)>>>(wk, 512,  wt, 2048);
    tposer<<<dim3(512 / 32,  DIN_ / 32),  dim3(32, 8)>>>(wv, 512,  wt, 2560);
    tposer<<<dim3(2048 / 32, DOUT_ / 32), dim3(32, 8)>>>(wo, 2048, wot, 0);

    // Fused QKV projection (tensor cores, tf32)
    gemm_tf32<<<dim3(DQKV_ / 128, SEQ_ / 128), 256, smem_sz>>>(xr, wt, QKV, DQKV_);

    // RMSNorm + RoPE
    norm_rope<<<(SEQ_ * NH_ * 32) / 256, 256>>>(QKV, qw, cosp, sinp, NH_, DQKV_);
    norm_rope<<<(SEQ_ * NKV_ * 32) / 256, 256>>>(QKV + 2048, kw, cosp, sinp, NKV_, DQKV_);

    // Causal GQA attention
    flash_attn<<<dim3(SEQ_ / FA_BQ, NH_), FA_BQ>>>();

    // Output projection (tensor cores, tf32)
    gemm_tf32<<<dim3(DIN_ / 128, SEQ_ / 128), 256, smem_sz>>>(A, wot, out, DIN_);
}

// round 7
// speedup vs baseline: 4.1248x; 2.1764x over previous
#include <cuda_runtime.h>
#include <cstdint>
#include <math.h>

#define SEQ_    2048
#define DIN_    2048
#define NH_     32
#define NKV_    8
#define HD_     64
#define DQKV_   3072            // Q(2048) | K(512) | V(512) fused columns
#define DOUT_   2048
#define GK_     2048            // GEMM K (both GEMMs have K=2048)

// ---------------------------------------------------------------------------
// Scratch (__device__ globals; allocation-free rule)
// ---------------------------------------------------------------------------
__device__ float g_xr[SEQ_ * DIN_];        // x rounded to tf32 grid
__device__ float g_wt[DQKV_ * DIN_];       // W_qkv^T [3072][2048], tf32-rounded
__device__ float g_wot[DIN_ * DOUT_];      // Wo^T    [2048][2048], tf32-rounded
__device__ float g_QKV[SEQ_ * DQKV_];      // [S, 3072]: Q | K | V
__device__ float g_A[SEQ_ * DOUT_];        // attention out, tf32-rounded

// ---------------------------------------------------------------------------
// Helpers (baseline PTX only — compute_103 has no 'a' features)
// ---------------------------------------------------------------------------
__device__ __forceinline__ uint32_t smem_u32(const void* p) {
    uint32_t a;
    asm("{ .reg .u64 t; cvta.to.shared.u64 t, %1; cvt.u32.u64 %0, t; }" : "=r"(a) : "l"(p));
    return a;
}
__device__ __forceinline__ float rnd_tf32(float f) {
    uint32_t u;
    asm("cvt.rna.tf32.f32 %0, %1;" : "=r"(u) : "f"(f));
    return __uint_as_float(u);
}
__device__ __forceinline__ void cpasync16(uint32_t dst, const void* src) {
    asm volatile("cp.async.cg.shared.global [%0], [%1], 16;" :: "r"(dst), "l"(src));
}
#define CP_COMMIT()  asm volatile("cp.async.commit_group;" ::: "memory")
#define CP_WAIT(n)   asm volatile("cp.async.wait_group %0;" :: "n"(n) : "memory")

__device__ __forceinline__ void mma_tf32(float* d, const float* a, const float* b) {
    asm volatile(
        "mma.sync.aligned.m16n8k8.row.col.f32.tf32.tf32.f32 "
        "{%0,%1,%2,%3}, {%4,%5,%6,%7}, {%8,%9}, {%0,%1,%2,%3};"
        : "+f"(d[0]), "+f"(d[1]), "+f"(d[2]), "+f"(d[3])
        : "r"(__float_as_uint(a[0])), "r"(__float_as_uint(a[1])),
          "r"(__float_as_uint(a[2])), "r"(__float_as_uint(a[3])),
          "r"(__float_as_uint(b[0])), "r"(__float_as_uint(b[1])));
}

// ---------------------------------------------------------------------------
// Prep kernels
// ---------------------------------------------------------------------------
__global__ void cvt_round4(const float* __restrict__ src, float* __restrict__ dst, int n4) {
    int i = blockIdx.x * blockDim.x + threadIdx.x;
    if (i >= n4) return;
    float4 v = ((const float4*)src)[i];
    v.x = rnd_tf32(v.x); v.y = rnd_tf32(v.y);
    v.z = rnd_tf32(v.z); v.w = rnd_tf32(v.w);
    ((float4*)dst)[i] = v;
}

// W[K=2048, ncols] -> out[(row_off+n)*2048 + k], tf32-rounded
__global__ void tposer(const float* __restrict__ W, int ncols,
                       float* __restrict__ out, int row_off) {
    __shared__ float t[32][33];
    int tx = threadIdx.x, ty = threadIdx.y;
    int x = blockIdx.x * 32 + tx;
    int y = blockIdx.y * 32 + ty;
#pragma unroll
    for (int i = 0; i < 32; i += 8)
        t[ty + i][tx] = W[(size_t)(y + i) * ncols + x];
    __syncthreads();
    int n = blockIdx.x * 32 + ty;
    int k = blockIdx.y * 32 + tx;
#pragma unroll
    for (int i = 0; i < 32; i += 8)
        out[(size_t)(row_off + n + i) * GK_ + k] = rnd_tf32(t[tx][ty + i]);
}

// Round the K|V column region of g_QKV (cols 2048..3071) to tf32 grid, in place
__global__ void round_kv() {
    int i = blockIdx.x * blockDim.x + threadIdx.x;   // over 2048*256 float4
    int row = i >> 8, c = i & 255;
    float4* p = (float4*)(g_QKV + (size_t)row * DQKV_ + 2048) + c;
    float4 v = *p;
    v.x = rnd_tf32(v.x); v.y = rnd_tf32(v.y);
    v.z = rnd_tf32(v.z); v.w = rnd_tf32(v.w);
    *p = v;
}

// ---------------------------------------------------------------------------
// tf32 mma.sync GEMM (unchanged from R6): C = A[M,2048] @ Bt[N,2048]^T
// ---------------------------------------------------------------------------
#define NCH32_  (GK_ / 32)
#define KPAD_   36
#define STG_F_  (2 * 128 * KPAD_)

__global__ __launch_bounds__(256) void gemm_tf32(
    const float* __restrict__ A, const float* __restrict__ Bt,
    float* __restrict__ C, int ldc)
{
    extern __shared__ float sm[];
    const int tid = threadIdx.x;
    const int wid = tid >> 5, lane = tid & 31;
    const int bm = blockIdx.y * 128, bn = blockIdx.x * 128;
    const int warp_m = (wid & 1) * 64, warp_n = (wid >> 1) * 32;
    const int tr = lane >> 2, tc = lane & 3;

    float acc[4][4][4];
#pragma unroll
    for (int i = 0; i < 4; i++)
#pragma unroll
        for (int j = 0; j < 4; j++)
#pragma unroll
            for (int r = 0; r < 4; r++) acc[i][j][r] = 0.f;

    const float* Ag = A + (size_t)bm * GK_;
    const float* Bg = Bt + (size_t)bn * GK_;
    const int lrow = tid >> 3;
    const int lq = tid & 7;
    uint32_t sbase = smem_u32(sm);

    {
        uint32_t sA = sbase;
        uint32_t sB = sbase + 128 * KPAD_ * 4;
#pragma unroll
        for (int i = 0; i < 4; i++) {
            int row = lrow + i * 32;
            uint32_t off = (uint32_t)(row * KPAD_ + lq * 4) * 4;
            cpasync16(sA + off, Ag + (size_t)row * GK_ + lq * 4);
            cpasync16(sB + off, Bg + (size_t)row * GK_ + lq * 4);
        }
        CP_COMMIT();
    }

    for (int c = 0; c < NCH32_; c++) {
        if (c + 1 < NCH32_) {
            const int k0 = (c + 1) * 32;
            uint32_t sA = sbase + (uint32_t)((c + 1) & 1) * STG_F_ * 4;
            uint32_t sB = sA + 128 * KPAD_ * 4;
#pragma unroll
            for (int i = 0; i < 4; i++) {
                int row = lrow + i * 32;
                uint32_t off = (uint32_t)(row * KPAD_ + lq * 4) * 4;
                cpasync16(sA + off, Ag + (size_t)row * GK_ + k0 + lq * 4);
                cpasync16(sB + off, Bg + (size_t)row * GK_ + k0 + lq * 4);
            }
            CP_COMMIT();
            CP_WAIT(1);
        } else {
            CP_WAIT(0);
        }
        __syncthreads();

        const float* As = sm + (c & 1) * STG_F_;
        const float* Bs = As + 128 * KPAD_;

#pragma unroll
        for (int kk = 0; kk < 4; kk++) {
            const int kb = kk * 8;
            float a[4][4], b[4][2];
#pragma unroll
            for (int mt = 0; mt < 4; mt++) {
                const float* ap = As + (warp_m + mt * 16 + tr) * KPAD_ + kb + tc;
                a[mt][0] = ap[0];
                a[mt][1] = ap[8 * KPAD_];
                a[mt][2] = ap[4];
                a[mt][3] = ap[8 * KPAD_ + 4];
            }
#pragma unroll
            for (int nt = 0; nt < 4; nt++) {
                const float* bp = Bs + (warp_n + nt * 8 + tr) * KPAD_ + kb + tc;
                b[nt][0] = bp[0];
                b[nt][1] = bp[4];
            }
#pragma unroll
            for (int mt = 0; mt < 4; mt++)
#pragma unroll
                for (int nt = 0; nt < 4; nt++)
                    mma_tf32(acc[mt][nt], a[mt], b[nt]);
        }
        __syncthreads();
    }

#pragma unroll
    for (int mt = 0; mt < 4; mt++)
#pragma unroll
        for (int nt = 0; nt < 4; nt++) {
            int row = bm + warp_m + mt * 16 + tr;
            int col = bn + warp_n + nt * 8 + 2 * tc;
            *(float2*)(C + (size_t)row * ldc + col) =
                make_float2(acc[mt][nt][0], acc[mt][nt][1]);
            *(float2*)(C + (size_t)(row + 8) * ldc + col) =
                make_float2(acc[mt][nt][2], acc[mt][nt][3]);
        }
}

// ---------------------------------------------------------------------------
// Fused RMSNorm + RoPE, in place on a column slice of g_QKV.
// ---------------------------------------------------------------------------
__global__ void norm_rope(float* __restrict__ X, const float* __restrict__ w,
                          const float* __restrict__ cosp, const float* __restrict__ sinp,
                          int nheads, int rowdim) {
    int gwarp = (blockIdx.x * blockDim.x + threadIdx.x) >> 5;
    int lane = threadIdx.x & 31;
    int s = gwarp / nheads;
    int h = gwarp % nheads;
    if (s >= SEQ_) return;

    float* p = X + (size_t)s * rowdim + h * HD_;
    float x0 = p[lane];
    float x1 = p[lane + 32];

    float ss = x0 * x0 + x1 * x1;
#pragma unroll
    for (int off = 16; off; off >>= 1) ss += __shfl_xor_sync(0xFFFFFFFFu, ss, off);
    float r = rsqrtf(ss * (1.f / 64.f) + 1e-6f);

    x0 = x0 * r * w[lane];
    x1 = x1 * r * w[lane + 32];

    float c0 = cosp[s * HD_ + lane],      s0 = sinp[s * HD_ + lane];
    float c1 = cosp[s * HD_ + lane + 32], s1 = sinp[s * HD_ + lane + 32];

    p[lane]      = x0 * c0 - x1 * s0;
    p[lane + 32] = x1 * c1 + x0 * s1;
}

// ---------------------------------------------------------------------------
// Tensor-core causal GQA flash attention (tf32 mma.sync).
// CTA = (q-block of 128, head). 8 warps, 16 q-rows each.
// smem: Qs(stride 68, reused as Ps stride 36) | Ks[2](stride 68) | Vs[2](stride 72)
// ---------------------------------------------------------------------------
#define QS_ST  68
#define PS_ST  36
#define KS_ST  68
#define VS_ST  72
#define OFF_K  (128 * QS_ST)                 // 8704 floats
#define OFF_V  (OFF_K + 2 * 32 * KS_ST)      // 13056
#define FA_SMF (OFF_V + 2 * 32 * VS_ST)      // 17664 floats = 70656 B

__global__ __launch_bounds__(256, 2) void flash_mma() {
    extern __shared__ float sm[];
    const int tid = threadIdx.x;
    const int w = tid >> 5, lane = tid & 31;
    const int tr = lane >> 2, tc = lane & 3;
    const int h = blockIdx.y;
    const int q0 = blockIdx.x * 128;
    const int kvh = h >> 2;

    float* Qs = sm;                 // [128][68]
    float* Ps = sm;                 // [128][36] (reuse after Q frags extracted)
    float* Ks = sm + OFF_K;         // [2][32][68]
    float* Vs = sm + OFF_V;         // [2][32][72]
    const uint32_t sb = smem_u32(sm);

    // ---- stage Q to smem (float4), then extract per-warp fragments ----
    {
        const float* Qg = g_QKV + (size_t)q0 * DQKV_ + h * HD_;
#pragma unroll
        for (int i = 0; i < 8; i++) {
            int idx = tid + i * 256;            // 2048 float4
            int row = idx >> 4, c4 = idx & 15;
            *(float4*)&Qs[row * QS_ST + c4 * 4] =
                *(const float4*)(Qg + (size_t)row * DQKV_ + c4 * 4);
        }
    }
    __syncthreads();

    float q[8][4];
    {
        const float* qp = Qs + (w * 16 + tr) * QS_ST + tc;
#pragma unroll
        for (int ks = 0; ks < 8; ks++) {
            q[ks][0] = rnd_tf32(qp[ks * 8] * 0.125f);
            q[ks][1] = rnd_tf32(qp[8 * QS_ST + ks * 8] * 0.125f);
            q[ks][2] = rnd_tf32(qp[ks * 8 + 4] * 0.125f);
            q[ks][3] = rnd_tf32(qp[8 * QS_ST + ks * 8 + 4] * 0.125f);
        }
    }
    __syncthreads();   // Qs region may now be reused as Ps

    float o[8][4];
#pragma unroll
    for (int nf = 0; nf < 8; nf++)
#pragma unroll
        for (int r = 0; r < 4; r++) o[nf][r] = 0.f;
    float m0 = -1e30f, m1 = -1e30f, l0 = 0.f, l1 = 0.f;

    const int ntiles = (q0 + 128) / 32;
    const float* Kg = g_QKV + 2048 + kvh * HD_;
    const float* Vg = g_QKV + 2560 + kvh * HD_;

    // prefetch tile 0
    {
#pragma unroll
        for (int j = 0; j < 2; j++) {
            int ci = tid + j * 256;             // 512 chunks
            int r = ci >> 4, q4 = ci & 15;
            cpasync16(sb + (OFF_K + r * KS_ST + q4 * 4) * 4,
                      Kg + (size_t)r * DQKV_ + q4 * 4);
            cpasync16(sb + (OFF_V + r * VS_ST + q4 * 4) * 4,
                      Vg + (size_t)r * DQKV_ + q4 * 4);
        }
        CP_COMMIT();
    }

    for (int t = 0; t < ntiles; t++) {
        const int k0 = t * 32;
        if (t + 1 < ntiles) {
            const int kn = (t + 1) * 32;
            const int buf = (t + 1) & 1;
#pragma unroll
            for (int j = 0; j < 2; j++) {
                int ci = tid + j * 256;
                int r = ci >> 4, q4 = ci & 15;
                cpasync16(sb + (OFF_K + (buf * 32 + r) * KS_ST + q4 * 4) * 4,
                          Kg + (size_t)(kn + r) * DQKV_ + q4 * 4);
                cpasync16(sb + (OFF_V + (buf * 32 + r) * VS_ST + q4 * 4) * 4,
                          Vg + (size_t)(kn + r) * DQKV_ + q4 * 4);
            }
            CP_COMMIT();
            CP_WAIT(1);
        } else {
            CP_WAIT(0);
        }
        __syncthreads();

        // warp-level skip: all rows of this warp < k0 -> fully masked tile
        if (k0 <= q0 + w * 16 + 15) {
            const float* Kt = Ks + (t & 1) * 32 * KS_ST;
            const float* Vt = Vs + (t & 1) * 32 * VS_ST;

            // ---- scores S[16][32] = Q @ K^T ----
            float s[4][4];
#pragma unroll
            for (int nf = 0; nf < 4; nf++) {
                s[nf][0] = s[nf][1] = s[nf][2] = s[nf][3] = 0.f;
                const float* bp = Kt + (nf * 8 + tr) * KS_ST + tc;
#pragma unroll
                for (int ks = 0; ks < 8; ks++) {
                    float b[2] = { bp[ks * 8], bp[ks * 8 + 4] };
                    mma_tf32(s[nf], q[ks], b);
                }
            }

            // ---- causal mask ----
            if (k0 + 31 > q0 + w * 16) {
                const int r0 = q0 + w * 16 + tr, r1 = r0 + 8;
                const int cb = k0 + 2 * tc;
#pragma unroll
                for (int nf = 0; nf < 4; nf++) {
                    int c0 = cb + nf * 8, c1 = c0 + 1;
                    if (c0 > r0) s[nf][0] = -1e30f;
                    if (c1 > r0) s[nf][1] = -1e30f;
                    if (c0 > r1) s[nf][2] = -1e30f;
                    if (c1 > r1) s[nf][3] = -1e30f;
                }
            }

            // ---- online softmax ----
            float t0 = fmaxf(fmaxf(s[0][0], s[0][1]), fmaxf(s[1][0], s[1][1]));
            t0 = fmaxf(t0, fmaxf(fmaxf(s[2][0], s[2][1]), fmaxf(s[3][0], s[3][1])));
            float t1 = fmaxf(fmaxf(s[0][2], s[0][3]), fmaxf(s[1][2], s[1][3]));
            t1 = fmaxf(t1, fmaxf(fmaxf(s[2][2], s[2][3]), fmaxf(s[3][2], s[3][3])));
            t0 = fmaxf(t0, __shfl_xor_sync(0xFFFFFFFFu, t0, 1));
            t0 = fmaxf(t0, __shfl_xor_sync(0xFFFFFFFFu, t0, 2));
            t1 = fmaxf(t1, __shfl_xor_sync(0xFFFFFFFFu, t1, 1));
            t1 = fmaxf(t1, __shfl_xor_sync(0xFFFFFFFFu, t1, 2));
            const float mt0 = fmaxf(m0, t0), mt1 = fmaxf(m1, t1);
            const float corr0 = __expf(m0 - mt0), corr1 = __expf(m1 - mt1);
            m0 = mt0; m1 = mt1;

            float* prow0 = Ps + (w * 16 + tr) * PS_ST + 2 * tc;
            float* prow1 = prow0 + 8 * PS_ST;
            float sum0 = 0.f, sum1 = 0.f;
#pragma unroll
            for (int nf = 0; nf < 4; nf++) {
                float p0 = rnd_tf32(__expf(s[nf][0] - mt0));
                float p1 = rnd_tf32(__expf(s[nf][1] - mt0));
                float p2 = rnd_tf32(__expf(s[nf][2] - mt1));
                float p3 = rnd_tf32(__expf(s[nf][3] - mt1));
                sum0 += p0 + p1; sum1 += p2 + p3;
                *(float2*)(prow0 + nf * 8) = make_float2(p0, p1);
                *(float2*)(prow1 + nf * 8) = make_float2(p2, p3);
            }
            sum0 += __shfl_xor_sync(0xFFFFFFFFu, sum0, 1);
            sum0 += __shfl_xor_sync(0xFFFFFFFFu, sum0, 2);
            sum1 += __shfl_xor_sync(0xFFFFFFFFu, sum1, 1);
            sum1 += __shfl_xor_sync(0xFFFFFFFFu, sum1, 2);
            l0 = l0 * corr0 + sum0;
            l1 = l1 * corr1 + sum1;

#pragma unroll
            for (int nf = 0; nf < 8; nf++) {
                o[nf][0] *= corr0; o[nf][1] *= corr0;
                o[nf][2] *= corr1; o[nf][3] *= corr1;
            }
            __syncwarp();

            // ---- O += P @ V ----
            const float* pa = Ps + (w * 16 + tr) * PS_ST + tc;
#pragma unroll
            for (int ks = 0; ks < 4; ks++) {
                float a[4] = { pa[ks * 8], pa[8 * PS_ST + ks * 8],
                               pa[ks * 8 + 4], pa[8 * PS_ST + ks * 8 + 4] };
                const float* vb = Vt + (ks * 8 + tc) * VS_ST + tr;
#pragma unroll
                for (int nf = 0; nf < 8; nf++) {
                    float b[2] = { vb[nf * 8], vb[4 * VS_ST + nf * 8] };
                    mma_tf32(o[nf], a, b);
                }
            }
            __syncwarp();
        }
        __syncthreads();   // all warps done with buf t before it is overwritten
    }

    // ---- epilogue ----
    const float inv0 = 1.f / l0, inv1 = 1.f / l1;
    const int r0 = q0 + w * 16 + tr;
    float* Og = g_A + (size_t)r0 * DOUT_ + h * HD_ + 2 * tc;
#pragma unroll
    for (int nf = 0; nf < 8; nf++) {
        *(float2*)(Og + nf * 8) =
            make_float2(rnd_tf32(o[nf][0] * inv0), rnd_tf32(o[nf][1] * inv0));
        *(float2*)(Og + 8 * DOUT_ + nf * 8) =
            make_float2(rnd_tf32(o[nf][2] * inv1), rnd_tf32(o[nf][3] * inv1));
    }
}

// ---------------------------------------------------------------------------
extern "C" void kernel_launch(void* const* d_in, const int* in_sizes, int n_in,
                              void* d_out, int out_size) {
    const float* x    = (const float*)d_in[0];
    const float* cosp = (const float*)d_in[1];
    const float* sinp = (const float*)d_in[2];
    const float* wq   = (const float*)d_in[3];
    const float* wk   = (const float*)d_in[4];
    const float* wv   = (const float*)d_in[5];
    const float* wo   = (const float*)d_in[6];
    const float* qw   = (const float*)d_in[7];
    const float* kw   = (const float*)d_in[8];
    float* out = (float*)d_out;

    float *xr, *wt, *wot, *QKV, *A;
    cudaGetSymbolAddress((void**)&xr,  g_xr);
    cudaGetSymbolAddress((void**)&wt,  g_wt);
    cudaGetSymbolAddress((void**)&wot, g_wot);
    cudaGetSymbolAddress((void**)&QKV, g_QKV);
    cudaGetSymbolAddress((void**)&A,   g_A);

    const int smem_sz = 2 * STG_F_ * 4;   // 73728 B
    cudaFuncSetAttribute(gemm_tf32, cudaFuncAttributeMaxDynamicSharedMemorySize, smem_sz);
    const int fa_smem = FA_SMF * 4;       // 70656 B
    cudaFuncSetAttribute(flash_mma, cudaFuncAttributeMaxDynamicSharedMemorySize, fa_smem);

    // Prep: round x; transpose+round weights
    cvt_round4<<<(SEQ_ * DIN_ / 4 + 255) / 256, 256>>>(x, xr, SEQ_ * DIN_ / 4);
    tposer<<<dim3(2048 / 32, DIN_ / 32),  dim3(32, 8)>>>(wq, 2048, wt, 0);
    tposer<<<dim3(512 / 32,  DIN_ / 32),  dim3(32, 8)>>>(wk, 512,  wt, 2048);
    tposer<<<dim3(512 / 32,  DIN_ / 32),  dim3(32, 8)>>>(wv, 512,  wt, 2560);
    tposer<<<dim3(2048 / 32, DOUT_ / 32), dim3(32, 8)>>>(wo, 2048, wot, 0);

    // Fused QKV projection (tf32 tensor cores)
    gemm_tf32<<<dim3(DQKV_ / 128, SEQ_ / 128), 256, smem_sz>>>(xr, wt, QKV, DQKV_);

    // RMSNorm + RoPE, then round K|V region to tf32 grid
    norm_rope<<<(SEQ_ * NH_ * 32) / 256, 256>>>(QKV, qw, cosp, sinp, NH_, DQKV_);
    norm_rope<<<(SEQ_ * NKV_ * 32) / 256, 256>>>(QKV + 2048, kw, cosp, sinp, NKV_, DQKV_);
    round_kv<<<SEQ_ * 256 / 256, 256>>>();

    // Tensor-core causal GQA attention
    flash_mma<<<dim3(SEQ_ / 128, NH_), 256, fa_smem>>>();

    // Output projection (tf32 tensor cores)
    gemm_tf32<<<dim3(DIN_ / 128, SEQ_ / 128), 256, smem_sz>>>(A, wot, out, DIN_);
}